// round 17
// baseline (speedup 1.0000x reference)
#include <cuda_runtime.h>
#include <stdint.h>

// RVAEModel: out[b, c, g] = weight[idx[b, g], c]
//   idx:    [256, 64]  (int32 OR int64 — detected in-warp)
//   weight: fp32 [1024, 1024]
//   out:    fp32 [256, 1024, 8, 8] (= [256, 1024, 64])
//
// WARP-AUTONOMOUS pipelines — zero __syncthreads. Each warp owns
// (b, 16-g chunk, 256-c quarter) and runs its own 8-subtile (32 c each)
// cp.async pipeline over a private 3-buffer smem ring (3 x 2KB):
//   iter h: wait_group (exact: allow {2,1,...,1,0}) -> __syncwarp ->
//   gather(h+2) into freed buffer -> LDS.128 x4 -> reg 4x4 transpose ->
//   STG.128 x4.
// Tile 16g x 8 float4: gather swizzle col = c4 ^ (g'>>2); LDS phase lanes
// (q fixed, uc=0..7) hit banks uc^q -> conflict-free; stores are dense 64B
// segments. 1024 CTAs x 4 warps = 4096 independent pipelines.

static constexpr int BS = 256;
static constexpr int M  = 64;    // tokens per sample (g)
static constexpr int C  = 1024;  // channels
static constexpr int NT = 8;     // subtiles per warp
static constexpr int SC = 32;    // subtile c-width
static constexpr int NB = 3;     // ring depth per warp

__global__ __launch_bounds__(128)
void rvae_gather_transpose(const void*  __restrict__ idx_raw,
                           const float* __restrict__ w,
                           float*       __restrict__ out)
{
    const int b   = blockIdx.y;
    const int cq  = blockIdx.x;       // c-quarter (0..3), 256 channels
    const int t   = threadIdx.x;      // 128 threads = 4 autonomous warps
    const int wrp = t >> 5;
    const int l   = t & 31;

    // Per-warp private ring: 4 warps x 3 bufs x (16g x 8 float4 = 2KB).
    __shared__ __align__(128) float4 tin[4][NB][16 * 8];

    // ---- in-warp dtype detect (first 64 indices: 512B probe, in-bounds
    // under both interpretations; P[misdetect] ~ 1024^-32 per warp).
    const unsigned int probe =
        reinterpret_cast<const unsigned int*>(idx_raw)[2 * (t & 63) + 1];
    const bool is32 = __any_sync(0xffffffffu, probe != 0u);

    // ---- gather lane roles: local g' = l>>1 (0..15), c4 = (l&1) + 2i.
    const int gl  = l >> 1;
    const int c4b = l & 1;
    const int ge  = b * M + 16 * wrp + gl; // idx element for this lane
    int row;
    if (is32) row = reinterpret_cast<const int*>(idx_raw)[ge];
    else      row = (int)reinterpret_cast<const long long*>(idx_raw)[ge];

    auto gather = [&](int h) {
        const int c0  = cq * 256 + SC * h;
        float4*   buf = tin[wrp][h % NB];
        #pragma unroll
        for (int i = 0; i < 4; i++) {
            const int c4 = c4b + 2 * i; // 0..7 over (i, l&1)
            const float*   src = w + (size_t)row * C + c0 + (c4 << 2);
            const uint32_t dst = (uint32_t)__cvta_generic_to_shared(
                &buf[gl * 8 + (c4 ^ (gl >> 2))]);
            asm volatile("cp.async.cg.shared.global [%0], [%1], 16;"
                         :: "r"(dst), "l"(src) : "memory");
        }
        asm volatile("cp.async.commit_group;" ::: "memory");
    };

    gather(0);
    gather(1);
    gather(2);

    // ---- transpose lane roles: q = l>>3 (g-quad 0..3), uc = l&7 (c-quad).
    const int q  = l >> 3;
    const int uc = l & 7;
    const int sw = uc ^ q; // swizzled tin column ((4q+k)>>2 == q)

    #pragma unroll
    for (int h = 0; h < NT; h++) {
        // Exact per-warp accounting: issued tiles = 0..max(2, h+1); need 0..h.
        const int allow = (h == 0) ? 2 : (h < NT - 1) ? 1 : 0;
        if (allow == 2)      asm volatile("cp.async.wait_group 2;" ::: "memory");
        else if (allow == 1) asm volatile("cp.async.wait_group 1;" ::: "memory");
        else                 asm volatile("cp.async.wait_group 0;" ::: "memory");
        __syncwarp(); // publishes tile h within warp; proves tile h-1 consumed

        // Buffer (h+2)%3 == (h-1)%3 free (all lanes past LDS of h-1).
        if (h >= 1 && h + 2 < NT) gather(h + 2);

        const float4* ti = tin[wrp][h % NB];
        const float4 r0 = ti[(4 * q + 0) * 8 + sw];
        const float4 r1 = ti[(4 * q + 1) * 8 + sw];
        const float4 r2 = ti[(4 * q + 2) * 8 + sw];
        const float4 r3 = ti[(4 * q + 3) * 8 + sw];

        // out[b, cq*256 + 32h + 4uc + j, 16*wrp + 4q + k]
        float* ob = out + (size_t)b * (C * M)
                        + (size_t)(cq * 256 + SC * h) * M + 16 * wrp + 4 * q;
        *reinterpret_cast<float4*>(ob + (4 * uc + 0) * M) = float4{r0.x, r1.x, r2.x, r3.x};
        *reinterpret_cast<float4*>(ob + (4 * uc + 1) * M) = float4{r0.y, r1.y, r2.y, r3.y};
        *reinterpret_cast<float4*>(ob + (4 * uc + 2) * M) = float4{r0.z, r1.z, r2.z, r3.z};
        *reinterpret_cast<float4*>(ob + (4 * uc + 3) * M) = float4{r0.w, r1.w, r2.w, r3.w};
    }
}

extern "C" void kernel_launch(void* const* d_in, const int* in_sizes, int n_in,
                              void* d_out, int out_size)
{
    // indices: 16384 elements; weight: 1048576 elements (fp32)
    const void*  idx;
    const float* w;
    if (in_sizes[0] == BS * M) {
        idx = d_in[0];
        w   = (const float*)d_in[1];
    } else {
        idx = d_in[1];
        w   = (const float*)d_in[0];
    }

    dim3 grid(4, BS); // (c-quarter, b) = 1024 blocks x 4 autonomous warps
    rvae_gather_transpose<<<grid, 128>>>(idx, w, (float*)d_out);
}